// round 12
// baseline (speedup 1.0000x reference)
#include <cuda_runtime.h>
#include <cuda_bf16.h>
#include <math.h>
#include <stdint.h>

// ---------------------------------------------------------------------------
// WaveNet inference, flat-time-domain form, bf16-split mma.sync GEMMs.
// R10 structure (direct-LDG mainloop, 128-thread blocks) + software-pipelined
// B-operand prefetch (double-buffered registers, one kt ahead).
//
// Per layer i (d = 2^(i%10)):
//   p = (-L) mod d   (prepend p zeros)
//   gated[t] = tanh(Wf0 x[t] + Wf1 x[t+d]) * sigmoid(Wg0 x[t] + Wg1 x[t+d])
//   skip[-Nout:] += Wskip * gated
//   x_new[t] = Wres * gated[t] + x[t+d]
//   L = L + p - d
// End: out = end2 @ relu(end1 @ relu(skip) + b1) + b2, last 4096 cols.
//
// Numerics: v = hi + lo (both bf16); GEMM = Ahi*Bhi + Ahi*Blo + Alo*Bhi with
// fp32 accumulate (~2^-16 relative error).
//
// Activations: two bf16 planes, channel-pairs packed in u32:
//   plane[(c>>1)*LSTR + t] = (bf16 c_even | bf16 c_odd<<16), right-aligned
// at column ECOL. Weights pre-packed into mma fragment order.
// ---------------------------------------------------------------------------

#define LSTR   7168
#define ECOL   7168
#define NLAYER 30

// activations (u32-packed bf16 pairs, 128 rows x LSTR)
__device__ uint32_t g_xHiA[128 * LSTR];
__device__ uint32_t g_xLoA[128 * LSTR];
__device__ uint32_t g_xHiB[128 * LSTR];
__device__ uint32_t g_xLoB[128 * LSTR];
__device__ uint32_t g_gHi [128 * LSTR];
__device__ uint32_t g_gLo [128 * LSTR];
// fp32 buffers
__device__ float g_sk[512 * LSTR];
__device__ float g_h1[512 * 4096];
__device__ float g_f0[256 * LSTR];
// fragment-packed weights (u32 = 2 bf16)
__device__ uint32_t g_wfgHi[NLAYER * 512 * 512 / 2];
__device__ uint32_t g_wfgLo[NLAYER * 512 * 512 / 2];
__device__ uint32_t g_resHi[NLAYER * 256 * 256 / 2];
__device__ uint32_t g_resLo[NLAYER * 256 * 256 / 2];
__device__ uint32_t g_skpHi[NLAYER * 512 * 256 / 2];
__device__ uint32_t g_skpLo[NLAYER * 512 * 256 / 2];

// ---------------------------------------------------------------------------
__device__ __forceinline__ void split2(float v, unsigned short& h, unsigned short& l) {
    __nv_bfloat16 bh = __float2bfloat16(v);
    float rest = v - __bfloat162float(bh);
    __nv_bfloat16 bl = __float2bfloat16(rest);
    h = __bfloat16_as_ushort(bh);
    l = __bfloat16_as_ushort(bl);
}
__device__ __forceinline__ float bf2f(unsigned short u) {
    return __bfloat162float(__ushort_as_bfloat16(u));
}

__device__ __forceinline__ void mma16816(float* c, const uint4& a, uint32_t b0, uint32_t b1) {
    asm volatile(
        "mma.sync.aligned.m16n8k16.row.col.f32.bf16.bf16.f32 "
        "{%0,%1,%2,%3},{%4,%5,%6,%7},{%8,%9},{%0,%1,%2,%3};\n"
        : "+f"(c[0]), "+f"(c[1]), "+f"(c[2]), "+f"(c[3])
        : "r"(a.x), "r"(a.y), "r"(a.z), "r"(a.w), "r"(b0), "r"(b1));
}

// ---------------------------------------------------------------------------
// Fragment packing (u32 index = ((kt*Mt + mt)*32 + lane)*4 + r).
// A frag rows: r0:(g,2tg) r1:(g+8,2tg) r2:(g,2tg+8) r3:(g+8,2tg+8)
// ---------------------------------------------------------------------------
__global__ void fragpack_gate(const float* __restrict__ fw, const float* __restrict__ gw,
                              uint32_t* __restrict__ Phi, uint32_t* __restrict__ Plo) {
    const int PER = 512 * 512 / 2;
    int idx = blockIdx.x * blockDim.x + threadIdx.x;
    if (idx >= NLAYER * PER) return;
    int i = idx / PER, rem = idx % PER;
    int r = rem & 3, lane = (rem >> 2) & 31, tile = rem >> 7;
    int mt = tile & 31, kt = tile >> 5;           // Mt = 32
    int g = lane >> 2, tg = lane & 3;
    int row = mt * 16 + g + ((r & 1) ? 8 : 0);    // 0..511 : F rows then G rows
    int k2  = kt * 16 + tg * 2 + ((r & 2) ? 8 : 0); // 0..511 : tap0 then tap1
    int tap = k2 >> 8, k = k2 & 255;
    float v0, v1;
    if (row < 256) {
        v0 = fw[(((size_t)i * 256 + row) * 256 + k) * 2 + tap];
        v1 = fw[(((size_t)i * 256 + row) * 256 + k + 1) * 2 + tap];
    } else {
        v0 = gw[(((size_t)i * 256 + row - 256) * 256 + k) * 2 + tap];
        v1 = gw[(((size_t)i * 256 + row - 256) * 256 + k + 1) * 2 + tap];
    }
    unsigned short h0, l0, h1, l1;
    split2(v0, h0, l0); split2(v1, h1, l1);
    Phi[idx] = (uint32_t)h0 | ((uint32_t)h1 << 16);
    Plo[idx] = (uint32_t)l0 | ((uint32_t)l1 << 16);
}

__global__ void fragpack_std(const float* __restrict__ W, int M, int K,
                             uint32_t* __restrict__ Phi, uint32_t* __restrict__ Plo) {
    int per = M * K / 2;
    int idx = blockIdx.x * blockDim.x + threadIdx.x;
    if (idx >= NLAYER * per) return;
    int i = idx / per, rem = idx % per;
    int Mt = M / 16;
    int r = rem & 3, lane = (rem >> 2) & 31, tile = rem >> 7;
    int mt = tile % Mt, kt = tile / Mt;
    int g = lane >> 2, tg = lane & 3;
    int row = mt * 16 + g + ((r & 1) ? 8 : 0);
    int k   = kt * 16 + tg * 2 + ((r & 2) ? 8 : 0);
    const float* Wl = W + (size_t)i * M * K;
    float v0 = Wl[(size_t)row * K + k];
    float v1 = Wl[(size_t)row * K + k + 1];
    unsigned short h0, l0, h1, l1;
    split2(v0, h0, l0); split2(v1, h1, l1);
    Phi[idx] = (uint32_t)h0 | ((uint32_t)h1 << 16);
    Plo[idx] = (uint32_t)l0 | ((uint32_t)l1 << 16);
}

// ---------------------------------------------------------------------------
// Utility kernels
// ---------------------------------------------------------------------------
__global__ void zero_pad2(uint32_t* __restrict__ Xhi, uint32_t* __restrict__ Xlo,
                          int col0, int p) {
    int idx = blockIdx.x * blockDim.x + threadIdx.x;
    if (idx >= 128 * p) return;
    int r = idx / p;
    int c = col0 + idx - r * p;
    Xhi[r * LSTR + c] = 0u;
    Xlo[r * LSTR + c] = 0u;
}

__global__ void split_start(const float* __restrict__ F, uint32_t* __restrict__ Xhi,
                            uint32_t* __restrict__ Xlo, int col0, int ncols) {
    int idx = blockIdx.x * blockDim.x + threadIdx.x;
    if (idx >= 128 * ncols) return;
    int r = idx / ncols;
    int c = col0 + idx - r * ncols;
    float v0 = F[(2 * r) * LSTR + c];
    float v1 = F[(2 * r + 1) * LSTR + c];
    unsigned short h0, l0, h1, l1;
    split2(v0, h0, l0); split2(v1, h1, l1);
    Xhi[r * LSTR + c] = (uint32_t)h0 | ((uint32_t)h1 << 16);
    Xlo[r * LSTR + c] = (uint32_t)l0 | ((uint32_t)l1 << 16);
}

// ---------------------------------------------------------------------------
// B-operand loaders (16 regs: bh0[4] bh1[4] bl0[4] bl1[4] packed in B[16]).
// ---------------------------------------------------------------------------
__device__ __forceinline__ void gate_loadB(
    const uint32_t* __restrict__ Xhi, const uint32_t* __restrict__ Xlo,
    int kt, int d, int xbase, int Nout, int n_warp, int g, int tg,
    uint32_t* __restrict__ B)
{
    const int shift = (kt >= 16) ? d : 0;
    const int krow = (kt & 15) * 8 + tg;
#pragma unroll
    for (int nt = 0; nt < 4; ++nt) {
        int n = n_warp + nt * 8 + g;
        bool ok = n < Nout;
        int o0 = krow * LSTR + xbase + n + shift;
        int o1 = o0 + 4 * LSTR;
        B[nt]      = ok ? Xhi[o0] : 0u;
        B[4 + nt]  = ok ? Xhi[o1] : 0u;
        B[8 + nt]  = ok ? Xlo[o0] : 0u;
        B[12 + nt] = ok ? Xlo[o1] : 0u;
    }
}

__device__ __forceinline__ void rs_loadB(
    const uint32_t* __restrict__ Ghi, const uint32_t* __restrict__ Glo,
    int kt, int gbase, int Nout, int n_warp, int g, int tg,
    uint32_t* __restrict__ B)
{
    const int krow = kt * 8 + tg;
#pragma unroll
    for (int nt = 0; nt < 4; ++nt) {
        int n = n_warp + nt * 8 + g;
        bool ok = n < Nout;
        int o0 = krow * LSTR + gbase + n;
        int o1 = o0 + 4 * LSTR;
        B[nt]      = ok ? Ghi[o0] : 0u;
        B[4 + nt]  = ok ? Ghi[o1] : 0u;
        B[8 + nt]  = ok ? Glo[o0] : 0u;
        B[12 + nt] = ok ? Glo[o1] : 0u;
    }
}

// ---------------------------------------------------------------------------
// Gate kernel: F,G = W[512x512] @ Xcat, epilogue tanh*sigmoid, split-store.
// Block 128 thr (4 warps, 1Mx4N). Block tile M=32(F)+32(G), N=128.
// B prefetched one kt ahead in registers (double-buffered).
// grid (ceil(Nout/128), 8).
// ---------------------------------------------------------------------------
__global__ __launch_bounds__(128) void gate_mma(
    const uint32_t* __restrict__ Whi, const uint32_t* __restrict__ Wlo,
    const uint32_t* __restrict__ Xhi, const uint32_t* __restrict__ Xlo,
    uint32_t* __restrict__ Ghi, uint32_t* __restrict__ Glo,
    int L, int d)
{
    const int Nout = L - d;
    const int xbase = ECOL - L;
    const int obase = ECOL - Nout;
    const int tid = threadIdx.x;
    const int lane = tid & 31, wn = tid >> 5;        // 4 warps: wn 0..3
    const int g = lane >> 2, tg = lane & 3;
    const int mF = blockIdx.y * 32;                  // 0..224 (F rows)
    const int n_warp = blockIdx.x * 128 + wn * 32;

    const uint4* Whi4 = (const uint4*)Whi;
    const uint4* Wlo4 = (const uint4*)Wlo;

    float CF[2][4][4] = {};
    float CG[2][4][4] = {};

    uint32_t Bbuf[2][16];
    gate_loadB(Xhi, Xlo, 0, d, xbase, Nout, n_warp, g, tg, Bbuf[0]);

#pragma unroll 2
    for (int kt = 0; kt < 32; ++kt) {
        if (kt + 1 < 32)
            gate_loadB(Xhi, Xlo, kt + 1, d, xbase, Nout, n_warp, g, tg,
                       Bbuf[(kt + 1) & 1]);
        const uint32_t* B = Bbuf[kt & 1];
#pragma unroll
        for (int mt = 0; mt < 2; ++mt) {
            int mtF = (mF >> 4) + mt;
            uint4 aFh = Whi4[(kt * 32 + mtF) * 32 + lane];
            uint4 aFl = Wlo4[(kt * 32 + mtF) * 32 + lane];
            uint4 aGh = Whi4[(kt * 32 + mtF + 16) * 32 + lane];
            uint4 aGl = Wlo4[(kt * 32 + mtF + 16) * 32 + lane];
#pragma unroll
            for (int nt = 0; nt < 4; ++nt) {
                mma16816(CF[mt][nt], aFh, B[nt], B[4 + nt]);
                mma16816(CF[mt][nt], aFh, B[8 + nt], B[12 + nt]);
                mma16816(CF[mt][nt], aFl, B[nt], B[4 + nt]);
                mma16816(CG[mt][nt], aGh, B[nt], B[4 + nt]);
                mma16816(CG[mt][nt], aGh, B[8 + nt], B[12 + nt]);
                mma16816(CG[mt][nt], aGl, B[nt], B[4 + nt]);
            }
        }
    }

    unsigned short* GhiS = (unsigned short*)Ghi;
    unsigned short* GloS = (unsigned short*)Glo;
#pragma unroll
    for (int mt = 0; mt < 2; ++mt)
#pragma unroll
        for (int nt = 0; nt < 4; ++nt)
#pragma unroll
            for (int r = 0; r < 4; ++r) {
                int n = n_warp + nt * 8 + 2 * tg + (r & 1);
                if (n >= Nout) continue;
                int m = mF + mt * 16 + g + ((r >= 2) ? 8 : 0);
                float f = CF[mt][nt][r];
                float q = CG[mt][nt][r];
                float fv = 2.f / (1.f + __expf(-2.f * f)) - 1.f;
                float sv = 1.f / (1.f + __expf(-q));
                float val = fv * sv;
                unsigned short h, l;
                split2(val, h, l);
                int u16i = ((m >> 1) * LSTR + obase + n) * 2 + (m & 1);
                GhiS[u16i] = h;
                GloS[u16i] = l;
            }
}

// ---------------------------------------------------------------------------
// Res+Skip kernel: M=768 (res 0..255, skip 256..767), K=256 over gated.
// Block 128 thr (4 warps, 1Mx4N). Block tile M=64, N=128; warp tile 64x32.
// B prefetched one kt ahead in registers. grid (ceil(Nout/128), 12).
// ---------------------------------------------------------------------------
__global__ __launch_bounds__(128) void resskip_mma(
    const uint32_t* __restrict__ RHi, const uint32_t* __restrict__ RLo,
    const uint32_t* __restrict__ SHi, const uint32_t* __restrict__ SLo,
    const uint32_t* __restrict__ Ghi, const uint32_t* __restrict__ Glo,
    const uint32_t* __restrict__ Xoldhi, const uint32_t* __restrict__ Xoldlo,
    uint32_t* __restrict__ Xnewhi, uint32_t* __restrict__ Xnewlo,
    float* __restrict__ skip, int Nout, int first)
{
    const int gbase = ECOL - Nout;
    const int tid = threadIdx.x;
    const int lane = tid & 31, wn = tid >> 5;        // 4 warps: wn 0..3
    const int g = lane >> 2, tg = lane & 3;
    const int m_warp = blockIdx.y * 64;              // 0..704
    const int n_warp = blockIdx.x * 128 + wn * 32;
    const bool isres = m_warp < 256;

    const uint4* Ah4;
    const uint4* Al4;
    int mtBase, Mt;
    if (isres) { Ah4 = (const uint4*)RHi; Al4 = (const uint4*)RLo; mtBase = m_warp >> 4;         Mt = 16; }
    else       { Ah4 = (const uint4*)SHi; Al4 = (const uint4*)SLo; mtBase = (m_warp - 256) >> 4; Mt = 32; }

    float C[4][4][4] = {};

    uint32_t Bbuf[2][16];
    rs_loadB(Ghi, Glo, 0, gbase, Nout, n_warp, g, tg, Bbuf[0]);

#pragma unroll 2
    for (int kt = 0; kt < 16; ++kt) {
        if (kt + 1 < 16)
            rs_loadB(Ghi, Glo, kt + 1, gbase, Nout, n_warp, g, tg,
                     Bbuf[(kt + 1) & 1]);
        const uint32_t* B = Bbuf[kt & 1];
#pragma unroll
        for (int mt = 0; mt < 4; ++mt) {
            uint4 ah = Ah4[(kt * Mt + mtBase + mt) * 32 + lane];
            uint4 al = Al4[(kt * Mt + mtBase + mt) * 32 + lane];
#pragma unroll
            for (int nt = 0; nt < 4; ++nt) {
                mma16816(C[mt][nt], ah, B[nt], B[4 + nt]);
                mma16816(C[mt][nt], ah, B[8 + nt], B[12 + nt]);
                mma16816(C[mt][nt], al, B[nt], B[4 + nt]);
            }
        }
    }

    const unsigned short* XoHS = (const unsigned short*)Xoldhi;
    const unsigned short* XoLS = (const unsigned short*)Xoldlo;
    unsigned short* XnHS = (unsigned short*)Xnewhi;
    unsigned short* XnLS = (unsigned short*)Xnewlo;
#pragma unroll
    for (int mt = 0; mt < 4; ++mt)
#pragma unroll
        for (int nt = 0; nt < 4; ++nt)
#pragma unroll
            for (int r = 0; r < 4; ++r) {
                int n = n_warp + nt * 8 + 2 * tg + (r & 1);
                if (n >= Nout) continue;
                int m = m_warp + mt * 16 + g + ((r >= 2) ? 8 : 0);
                int col = gbase + n;
                float v = C[mt][nt][r];
                if (isres) {
                    int u16i = ((m >> 1) * LSTR + col) * 2 + (m & 1);
                    v += bf2f(XoHS[u16i]) + bf2f(XoLS[u16i]);
                    unsigned short h, l;
                    split2(v, h, l);
                    XnHS[u16i] = h;
                    XnLS[u16i] = l;
                } else {
                    int ms = m - 256;
                    if (!first) v += skip[ms * LSTR + col];
                    skip[ms * LSTR + col] = v;
                }
            }
}

// ---------------------------------------------------------------------------
// SIMT fp32 GEMM for start/end convs: Y = W[MxK] @ X[KxN] (+bias/relu).
// ---------------------------------------------------------------------------
__global__ void lin_kernel(const float* __restrict__ W,
                           const float* __restrict__ X, int ldx,
                           const float* __restrict__ bias,
                           float* __restrict__ Y, int ldy,
                           int M, int K, int N, int relu_in, int relu_out) {
    const int t0 = blockIdx.x * 64;
    const int m0 = blockIdx.y * 64;
    const int tid = threadIdx.x;
    const int tx = tid & 15, ty = tid >> 4;

    __shared__ float Xs[16][64];
    __shared__ float Ws[64][16];

    float acc[4][4] = {};

    for (int kc = 0; kc < K; kc += 16) {
#pragma unroll
        for (int j = 0; j < 4; j++) {
            int e = tid + 256 * j;
            int r = e >> 6, c = e & 63;
            int t = t0 + c;
            float v = (t < N) ? X[(size_t)(kc + r) * ldx + t] : 0.f;
            if (relu_in) v = fmaxf(v, 0.f);
            Xs[r][c] = v;
            int mm = e >> 4, rr = e & 15;
            Ws[mm][rr] = W[(size_t)(m0 + mm) * K + kc + rr];
        }
        __syncthreads();
#pragma unroll
        for (int r = 0; r < 16; r++) {
            float b[4];
#pragma unroll
            for (int j = 0; j < 4; j++) b[j] = Xs[r][tx * 4 + j];
#pragma unroll
            for (int i = 0; i < 4; i++) {
                float a = Ws[ty * 4 + i][r];
#pragma unroll
                for (int j = 0; j < 4; j++) acc[i][j] += a * b[j];
            }
        }
        __syncthreads();
    }

#pragma unroll
    for (int i = 0; i < 4; i++) {
        int m = m0 + ty * 4 + i;
#pragma unroll
        for (int j = 0; j < 4; j++) {
            int t = t0 + tx * 4 + j;
            if (t >= N) continue;
            float v = acc[i][j];
            if (bias) v += bias[m];
            if (relu_out) v = fmaxf(v, 0.f);
            Y[(size_t)m * ldy + t] = v;
        }
    }
}

// ---------------------------------------------------------------------------
// Host orchestration (graph-capturable: kernel launches only).
// ---------------------------------------------------------------------------
extern "C" void kernel_launch(void* const* d_in, const int* in_sizes, int n_in,
                              void* d_out, int out_size) {
    (void)in_sizes; (void)n_in; (void)out_size;
    const float* input    = (const float*)d_in[0];
    const float* start_w  = (const float*)d_in[1];
    const float* filter_w = (const float*)d_in[2];
    const float* gate_w   = (const float*)d_in[3];
    const float* res_w    = (const float*)d_in[4];
    const float* skip_w   = (const float*)d_in[5];
    const float* end1_w   = (const float*)d_in[6];
    const float* end1_b   = (const float*)d_in[7];
    const float* end2_w   = (const float*)d_in[8];
    const float* end2_b   = (const float*)d_in[9];

    uint32_t *xHiA, *xLoA, *xHiB, *xLoB, *gHi, *gLo;
    uint32_t *wfgHi, *wfgLo, *resHi, *resLo, *skpHi, *skpLo;
    float *sk, *h1, *f0;
    cudaGetSymbolAddress((void**)&xHiA, g_xHiA);
    cudaGetSymbolAddress((void**)&xLoA, g_xLoA);
    cudaGetSymbolAddress((void**)&xHiB, g_xHiB);
    cudaGetSymbolAddress((void**)&xLoB, g_xLoB);
    cudaGetSymbolAddress((void**)&gHi,  g_gHi);
    cudaGetSymbolAddress((void**)&gLo,  g_gLo);
    cudaGetSymbolAddress((void**)&wfgHi, g_wfgHi);
    cudaGetSymbolAddress((void**)&wfgLo, g_wfgLo);
    cudaGetSymbolAddress((void**)&resHi, g_resHi);
    cudaGetSymbolAddress((void**)&resLo, g_resLo);
    cudaGetSymbolAddress((void**)&skpHi, g_skpHi);
    cudaGetSymbolAddress((void**)&skpLo, g_skpLo);
    cudaGetSymbolAddress((void**)&sk, g_sk);
    cudaGetSymbolAddress((void**)&h1, g_h1);
    cudaGetSymbolAddress((void**)&f0, g_f0);

    // Weight fragment packing (every call; deterministic).
    {
        int n = NLAYER * 512 * 512 / 2;
        fragpack_gate<<<(n + 255) / 256, 256>>>(filter_w, gate_w, wfgHi, wfgLo);
        n = NLAYER * 256 * 256 / 2;
        fragpack_std<<<(n + 255) / 256, 256>>>(res_w, 256, 256, resHi, resLo);
        n = NLAYER * 512 * 256 / 2;
        fragpack_std<<<(n + 255) / 256, 256>>>(skip_w, 512, 256, skpHi, skpLo);
    }

    // Start conv (fp32 SIMT) then split into bf16 planes, right-aligned.
    lin_kernel<<<dim3((7165 + 63) / 64, 4), 256>>>(
        start_w, input, 7165, nullptr, f0 + (ECOL - 7165), LSTR,
        256, 256, 7165, 0, 0);
    {
        int n = 128 * 7165;
        split_start<<<(n + 255) / 256, 256>>>(f0, xHiA, xLoA, ECOL - 7165, 7165);
    }

    int L = 7165;
    uint32_t *xcHi = xHiA, *xcLo = xLoA, *xnHi = xHiB, *xnLo = xLoB;

    for (int i = 0; i < NLAYER; i++) {
        int d = 1 << (i % 10);
        int p = (d - (L % d)) % d;
        if (p > 0) {
            zero_pad2<<<(128 * p + 255) / 256, 256>>>(xcHi, xcLo, ECOL - L - p, p);
            L += p;
        }
        int Nout = L - d;

        dim3 gg((Nout + 127) / 128, 8);
        gate_mma<<<gg, 128>>>(wfgHi + (size_t)i * 131072, wfgLo + (size_t)i * 131072,
                              xcHi, xcLo, gHi, gLo, L, d);

        dim3 gr((Nout + 127) / 128, 12);
        resskip_mma<<<gr, 128>>>(resHi + (size_t)i * 32768, resLo + (size_t)i * 32768,
                                 skpHi + (size_t)i * 65536, skpLo + (size_t)i * 65536,
                                 gHi, gLo, xcHi, xcLo, xnHi, xnLo,
                                 sk, Nout, i == 0 ? 1 : 0);
        uint32_t* t;
        t = xcHi; xcHi = xnHi; xnHi = t;
        t = xcLo; xcLo = xnLo; xnLo = t;
        L = Nout;
    }

    // End head on last 4096 columns (fp32 SIMT).
    lin_kernel<<<dim3(64, 8), 256>>>(
        end1_w, sk + (ECOL - 4096), LSTR, end1_b, h1, 4096,
        512, 512, 4096, 1, 1);
    lin_kernel<<<dim3(64, 4), 256>>>(
        end2_w, h1, 4096, end2_b, (float*)d_out, 4096,
        256, 512, 4096, 0, 0);
}

// round 13
// speedup vs baseline: 1.3702x; 1.3702x over previous
#include <cuda_runtime.h>
#include <cuda_bf16.h>
#include <math.h>
#include <stdint.h>

// ---------------------------------------------------------------------------
// WaveNet inference, flat-time-domain form, bf16-split mma.sync GEMMs.
// R10 structure (direct-LDG mainloop, 128-thread blocks — proven fastest).
// R13: zero-padding folded into gate load predicate (no zero_pad launches);
//      start conv writes split bf16 planes directly (no split_start pass).
//
// Per layer i (d = 2^(i%10)):
//   p = (-L) mod d   (prepend p zeros — virtual, via load masking)
//   gated[t] = tanh(Wf0 x[t] + Wf1 x[t+d]) * sigmoid(Wg0 x[t] + Wg1 x[t+d])
//   skip[-Nout:] += Wskip * gated
//   x_new[t] = Wres * gated[t] + x[t+d]
//   L = L + p - d
// End: out = end2 @ relu(end1 @ relu(skip) + b1) + b2, last 4096 cols.
//
// Numerics: v = hi + lo (both bf16); GEMM = Ahi*Bhi + Ahi*Blo + Alo*Bhi with
// fp32 accumulate (~2^-16 relative error).
//
// Activations: two bf16 planes, channel-pairs packed in u32:
//   plane[(c>>1)*LSTR + t] = (bf16 c_even | bf16 c_odd<<16), right-aligned
// at column ECOL. Weights pre-packed into mma fragment order.
// ---------------------------------------------------------------------------

#define LSTR   7168
#define ECOL   7168
#define NLAYER 30

// activations (u32-packed bf16 pairs, 128 rows x LSTR)
__device__ uint32_t g_xHiA[128 * LSTR];
__device__ uint32_t g_xLoA[128 * LSTR];
__device__ uint32_t g_xHiB[128 * LSTR];
__device__ uint32_t g_xLoB[128 * LSTR];
__device__ uint32_t g_gHi [128 * LSTR];
__device__ uint32_t g_gLo [128 * LSTR];
// fp32 buffers
__device__ float g_sk[512 * LSTR];
__device__ float g_h1[512 * 4096];
// fragment-packed weights (u32 = 2 bf16)
__device__ uint32_t g_wfgHi[NLAYER * 512 * 512 / 2];
__device__ uint32_t g_wfgLo[NLAYER * 512 * 512 / 2];
__device__ uint32_t g_resHi[NLAYER * 256 * 256 / 2];
__device__ uint32_t g_resLo[NLAYER * 256 * 256 / 2];
__device__ uint32_t g_skpHi[NLAYER * 512 * 256 / 2];
__device__ uint32_t g_skpLo[NLAYER * 512 * 256 / 2];

// ---------------------------------------------------------------------------
__device__ __forceinline__ void split2(float v, unsigned short& h, unsigned short& l) {
    __nv_bfloat16 bh = __float2bfloat16(v);
    float rest = v - __bfloat162float(bh);
    __nv_bfloat16 bl = __float2bfloat16(rest);
    h = __bfloat16_as_ushort(bh);
    l = __bfloat16_as_ushort(bl);
}
__device__ __forceinline__ float bf2f(unsigned short u) {
    return __bfloat162float(__ushort_as_bfloat16(u));
}

__device__ __forceinline__ void mma16816(float* c, const uint4& a, uint32_t b0, uint32_t b1) {
    asm volatile(
        "mma.sync.aligned.m16n8k16.row.col.f32.bf16.bf16.f32 "
        "{%0,%1,%2,%3},{%4,%5,%6,%7},{%8,%9},{%0,%1,%2,%3};\n"
        : "+f"(c[0]), "+f"(c[1]), "+f"(c[2]), "+f"(c[3])
        : "r"(a.x), "r"(a.y), "r"(a.z), "r"(a.w), "r"(b0), "r"(b1));
}

// ---------------------------------------------------------------------------
// Fragment packing (u32 index = ((kt*Mt + mt)*32 + lane)*4 + r).
// A frag rows: r0:(g,2tg) r1:(g+8,2tg) r2:(g,2tg+8) r3:(g+8,2tg+8)
// ---------------------------------------------------------------------------
__global__ void fragpack_gate(const float* __restrict__ fw, const float* __restrict__ gw,
                              uint32_t* __restrict__ Phi, uint32_t* __restrict__ Plo) {
    const int PER = 512 * 512 / 2;
    int idx = blockIdx.x * blockDim.x + threadIdx.x;
    if (idx >= NLAYER * PER) return;
    int i = idx / PER, rem = idx % PER;
    int r = rem & 3, lane = (rem >> 2) & 31, tile = rem >> 7;
    int mt = tile & 31, kt = tile >> 5;           // Mt = 32
    int g = lane >> 2, tg = lane & 3;
    int row = mt * 16 + g + ((r & 1) ? 8 : 0);    // 0..511 : F rows then G rows
    int k2  = kt * 16 + tg * 2 + ((r & 2) ? 8 : 0); // 0..511 : tap0 then tap1
    int tap = k2 >> 8, k = k2 & 255;
    float v0, v1;
    if (row < 256) {
        v0 = fw[(((size_t)i * 256 + row) * 256 + k) * 2 + tap];
        v1 = fw[(((size_t)i * 256 + row) * 256 + k + 1) * 2 + tap];
    } else {
        v0 = gw[(((size_t)i * 256 + row - 256) * 256 + k) * 2 + tap];
        v1 = gw[(((size_t)i * 256 + row - 256) * 256 + k + 1) * 2 + tap];
    }
    unsigned short h0, l0, h1, l1;
    split2(v0, h0, l0); split2(v1, h1, l1);
    Phi[idx] = (uint32_t)h0 | ((uint32_t)h1 << 16);
    Plo[idx] = (uint32_t)l0 | ((uint32_t)l1 << 16);
}

__global__ void fragpack_std(const float* __restrict__ W, int M, int K,
                             uint32_t* __restrict__ Phi, uint32_t* __restrict__ Plo) {
    int per = M * K / 2;
    int idx = blockIdx.x * blockDim.x + threadIdx.x;
    if (idx >= NLAYER * per) return;
    int i = idx / per, rem = idx % per;
    int Mt = M / 16;
    int r = rem & 3, lane = (rem >> 2) & 31, tile = rem >> 7;
    int mt = tile % Mt, kt = tile / Mt;
    int g = lane >> 2, tg = lane & 3;
    int row = mt * 16 + g + ((r & 1) ? 8 : 0);
    int k   = kt * 16 + tg * 2 + ((r & 2) ? 8 : 0);
    const float* Wl = W + (size_t)i * M * K;
    float v0 = Wl[(size_t)row * K + k];
    float v1 = Wl[(size_t)row * K + k + 1];
    unsigned short h0, l0, h1, l1;
    split2(v0, h0, l0); split2(v1, h1, l1);
    Phi[idx] = (uint32_t)h0 | ((uint32_t)h1 << 16);
    Plo[idx] = (uint32_t)l0 | ((uint32_t)l1 << 16);
}

// ---------------------------------------------------------------------------
// Start conv: fp32 SIMT GEMM, writes u32-packed bf16 hi/lo planes directly.
// Y[m][t] -> Xhi/Xlo[(m>>1)*LSTR + col0 + t]. M=256, K=256, N=7165.
// ---------------------------------------------------------------------------
__global__ void lin_start(const float* __restrict__ W, const float* __restrict__ X,
                          uint32_t* __restrict__ Xhi, uint32_t* __restrict__ Xlo,
                          int N, int col0) {
    const int t0 = blockIdx.x * 64;
    const int m0 = blockIdx.y * 64;
    const int tid = threadIdx.x;
    const int tx = tid & 15, ty = tid >> 4;

    __shared__ float Xs[16][64];
    __shared__ float Ws[64][16];

    float acc[4][4] = {};

    for (int kc = 0; kc < 256; kc += 16) {
#pragma unroll
        for (int j = 0; j < 4; j++) {
            int e = tid + 256 * j;
            int r = e >> 6, c = e & 63;
            int t = t0 + c;
            Xs[r][c] = (t < N) ? X[(size_t)(kc + r) * N + t] : 0.f;
            int mm = e >> 4, rr = e & 15;
            Ws[mm][rr] = W[(size_t)(m0 + mm) * 256 + kc + rr];
        }
        __syncthreads();
#pragma unroll
        for (int r = 0; r < 16; r++) {
            float b[4];
#pragma unroll
            for (int j = 0; j < 4; j++) b[j] = Xs[r][tx * 4 + j];
#pragma unroll
            for (int i = 0; i < 4; i++) {
                float a = Ws[ty * 4 + i][r];
#pragma unroll
                for (int j = 0; j < 4; j++) acc[i][j] += a * b[j];
            }
        }
        __syncthreads();
    }

#pragma unroll
    for (int j = 0; j < 4; j++) {
        int t = t0 + tx * 4 + j;
        if (t >= N) continue;
#pragma unroll
        for (int pi = 0; pi < 2; pi++) {
            int m = m0 + ty * 4 + 2 * pi;     // even channel of the pair
            unsigned short h0, l0, h1, l1;
            split2(acc[2 * pi][j], h0, l0);
            split2(acc[2 * pi + 1][j], h1, l1);
            Xhi[(m >> 1) * LSTR + col0 + t] = (uint32_t)h0 | ((uint32_t)h1 << 16);
            Xlo[(m >> 1) * LSTR + col0 + t] = (uint32_t)l0 | ((uint32_t)l1 << 16);
        }
    }
}

// ---------------------------------------------------------------------------
// Gate kernel: F,G = W[512x512] @ Xcat, epilogue tanh*sigmoid, split-store.
// Block 128 thr (4 warps, 1Mx4N). Block tile M=32(F)+32(G), N=128.
// Padding is virtual: tap0 loads masked to n >= p (pad region never written).
// grid (ceil(Nout/128), 8).
// ---------------------------------------------------------------------------
__global__ __launch_bounds__(128) void gate_mma(
    const uint32_t* __restrict__ Whi, const uint32_t* __restrict__ Wlo,
    const uint32_t* __restrict__ Xhi, const uint32_t* __restrict__ Xlo,
    uint32_t* __restrict__ Ghi, uint32_t* __restrict__ Glo,
    int L, int d, int p)
{
    const int Nout = L - d;
    const int xbase = ECOL - L;
    const int obase = ECOL - Nout;
    const int tid = threadIdx.x;
    const int lane = tid & 31, wn = tid >> 5;        // 4 warps: wn 0..3
    const int g = lane >> 2, tg = lane & 3;
    const int mF = blockIdx.y * 32;                  // 0..224 (F rows)
    const int n_warp = blockIdx.x * 128 + wn * 32;

    const uint4* Whi4 = (const uint4*)Whi;
    const uint4* Wlo4 = (const uint4*)Wlo;

    float CF[2][4][4] = {};
    float CG[2][4][4] = {};

    for (int kt = 0; kt < 32; ++kt) {
        const bool tap1 = (kt >= 16);
        const int shift = tap1 ? d : 0;
        const int krow = (kt & 15) * 8 + tg;
        uint32_t bh0[4], bh1[4], bl0[4], bl1[4];
#pragma unroll
        for (int nt = 0; nt < 4; ++nt) {
            int n = n_warp + nt * 8 + g;
            // tap0 reads virtual pad zeros for n < p; tap1 always valid data
            bool ok = (n < Nout) && (tap1 || n >= p);
            int o0 = krow * LSTR + xbase + n + shift;
            int o1 = o0 + 4 * LSTR;
            bh0[nt] = ok ? Xhi[o0] : 0u;
            bh1[nt] = ok ? Xhi[o1] : 0u;
            bl0[nt] = ok ? Xlo[o0] : 0u;
            bl1[nt] = ok ? Xlo[o1] : 0u;
        }
#pragma unroll
        for (int mt = 0; mt < 2; ++mt) {
            int mtF = (mF >> 4) + mt;
            uint4 aFh = Whi4[(kt * 32 + mtF) * 32 + lane];
            uint4 aFl = Wlo4[(kt * 32 + mtF) * 32 + lane];
            uint4 aGh = Whi4[(kt * 32 + mtF + 16) * 32 + lane];
            uint4 aGl = Wlo4[(kt * 32 + mtF + 16) * 32 + lane];
#pragma unroll
            for (int nt = 0; nt < 4; ++nt) {
                mma16816(CF[mt][nt], aFh, bh0[nt], bh1[nt]);
                mma16816(CF[mt][nt], aFh, bl0[nt], bl1[nt]);
                mma16816(CF[mt][nt], aFl, bh0[nt], bh1[nt]);
                mma16816(CG[mt][nt], aGh, bh0[nt], bh1[nt]);
                mma16816(CG[mt][nt], aGh, bl0[nt], bl1[nt]);
                mma16816(CG[mt][nt], aGl, bh0[nt], bh1[nt]);
            }
        }
    }

    unsigned short* GhiS = (unsigned short*)Ghi;
    unsigned short* GloS = (unsigned short*)Glo;
#pragma unroll
    for (int mt = 0; mt < 2; ++mt)
#pragma unroll
        for (int nt = 0; nt < 4; ++nt)
#pragma unroll
            for (int r = 0; r < 4; ++r) {
                int n = n_warp + nt * 8 + 2 * tg + (r & 1);
                if (n >= Nout) continue;
                int m = mF + mt * 16 + g + ((r >= 2) ? 8 : 0);
                float f = CF[mt][nt][r];
                float q = CG[mt][nt][r];
                float fv = 2.f / (1.f + __expf(-2.f * f)) - 1.f;
                float sv = 1.f / (1.f + __expf(-q));
                float val = fv * sv;
                unsigned short h, l;
                split2(val, h, l);
                int u16i = ((m >> 1) * LSTR + obase + n) * 2 + (m & 1);
                GhiS[u16i] = h;
                GloS[u16i] = l;
            }
}

// ---------------------------------------------------------------------------
// Res+Skip kernel: M=768 (res 0..255, skip 256..767), K=256 over gated.
// Block 128 thr (4 warps, 1Mx4N). Block tile M=64, N=128; warp tile 64x32.
// grid (ceil(Nout/128), 12).
// ---------------------------------------------------------------------------
__global__ __launch_bounds__(128) void resskip_mma(
    const uint32_t* __restrict__ RHi, const uint32_t* __restrict__ RLo,
    const uint32_t* __restrict__ SHi, const uint32_t* __restrict__ SLo,
    const uint32_t* __restrict__ Ghi, const uint32_t* __restrict__ Glo,
    const uint32_t* __restrict__ Xoldhi, const uint32_t* __restrict__ Xoldlo,
    uint32_t* __restrict__ Xnewhi, uint32_t* __restrict__ Xnewlo,
    float* __restrict__ skip, int Nout, int first)
{
    const int gbase = ECOL - Nout;
    const int tid = threadIdx.x;
    const int lane = tid & 31, wn = tid >> 5;        // 4 warps: wn 0..3
    const int g = lane >> 2, tg = lane & 3;
    const int m_warp = blockIdx.y * 64;              // 0..704
    const int n_warp = blockIdx.x * 128 + wn * 32;
    const bool isres = m_warp < 256;

    const uint4* Ah4;
    const uint4* Al4;
    int mtBase, Mt;
    if (isres) { Ah4 = (const uint4*)RHi; Al4 = (const uint4*)RLo; mtBase = m_warp >> 4;         Mt = 16; }
    else       { Ah4 = (const uint4*)SHi; Al4 = (const uint4*)SLo; mtBase = (m_warp - 256) >> 4; Mt = 32; }

    float C[4][4][4] = {};

    for (int kt = 0; kt < 16; ++kt) {
        const int krow = kt * 8 + tg;
        uint32_t bh0[4], bh1[4], bl0[4], bl1[4];
#pragma unroll
        for (int nt = 0; nt < 4; ++nt) {
            int n = n_warp + nt * 8 + g;
            bool ok = n < Nout;
            int o0 = krow * LSTR + gbase + n;
            int o1 = o0 + 4 * LSTR;
            bh0[nt] = ok ? Ghi[o0] : 0u;
            bh1[nt] = ok ? Ghi[o1] : 0u;
            bl0[nt] = ok ? Glo[o0] : 0u;
            bl1[nt] = ok ? Glo[o1] : 0u;
        }
#pragma unroll
        for (int mt = 0; mt < 4; ++mt) {
            uint4 ah = Ah4[(kt * Mt + mtBase + mt) * 32 + lane];
            uint4 al = Al4[(kt * Mt + mtBase + mt) * 32 + lane];
#pragma unroll
            for (int nt = 0; nt < 4; ++nt) {
                mma16816(C[mt][nt], ah, bh0[nt], bh1[nt]);
                mma16816(C[mt][nt], ah, bl0[nt], bl1[nt]);
                mma16816(C[mt][nt], al, bh0[nt], bh1[nt]);
            }
        }
    }

    const unsigned short* XoHS = (const unsigned short*)Xoldhi;
    const unsigned short* XoLS = (const unsigned short*)Xoldlo;
    unsigned short* XnHS = (unsigned short*)Xnewhi;
    unsigned short* XnLS = (unsigned short*)Xnewlo;
#pragma unroll
    for (int mt = 0; mt < 4; ++mt)
#pragma unroll
        for (int nt = 0; nt < 4; ++nt)
#pragma unroll
            for (int r = 0; r < 4; ++r) {
                int n = n_warp + nt * 8 + 2 * tg + (r & 1);
                if (n >= Nout) continue;
                int m = m_warp + mt * 16 + g + ((r >= 2) ? 8 : 0);
                int col = gbase + n;
                float v = C[mt][nt][r];
                if (isres) {
                    int u16i = ((m >> 1) * LSTR + col) * 2 + (m & 1);
                    v += bf2f(XoHS[u16i]) + bf2f(XoLS[u16i]);
                    unsigned short h, l;
                    split2(v, h, l);
                    XnHS[u16i] = h;
                    XnLS[u16i] = l;
                } else {
                    int ms = m - 256;
                    if (!first) v += skip[ms * LSTR + col];
                    skip[ms * LSTR + col] = v;
                }
            }
}

// ---------------------------------------------------------------------------
// SIMT fp32 GEMM for end convs: Y = W[MxK] @ X[KxN] (+bias/relu).
// ---------------------------------------------------------------------------
__global__ void lin_kernel(const float* __restrict__ W,
                           const float* __restrict__ X, int ldx,
                           const float* __restrict__ bias,
                           float* __restrict__ Y, int ldy,
                           int M, int K, int N, int relu_in, int relu_out) {
    const int t0 = blockIdx.x * 64;
    const int m0 = blockIdx.y * 64;
    const int tid = threadIdx.x;
    const int tx = tid & 15, ty = tid >> 4;

    __shared__ float Xs[16][64];
    __shared__ float Ws[64][16];

    float acc[4][4] = {};

    for (int kc = 0; kc < K; kc += 16) {
#pragma unroll
        for (int j = 0; j < 4; j++) {
            int e = tid + 256 * j;
            int r = e >> 6, c = e & 63;
            int t = t0 + c;
            float v = (t < N) ? X[(size_t)(kc + r) * ldx + t] : 0.f;
            if (relu_in) v = fmaxf(v, 0.f);
            Xs[r][c] = v;
            int mm = e >> 4, rr = e & 15;
            Ws[mm][rr] = W[(size_t)(m0 + mm) * K + kc + rr];
        }
        __syncthreads();
#pragma unroll
        for (int r = 0; r < 16; r++) {
            float b[4];
#pragma unroll
            for (int j = 0; j < 4; j++) b[j] = Xs[r][tx * 4 + j];
#pragma unroll
            for (int i = 0; i < 4; i++) {
                float a = Ws[ty * 4 + i][r];
#pragma unroll
                for (int j = 0; j < 4; j++) acc[i][j] += a * b[j];
            }
        }
        __syncthreads();
    }

#pragma unroll
    for (int i = 0; i < 4; i++) {
        int m = m0 + ty * 4 + i;
#pragma unroll
        for (int j = 0; j < 4; j++) {
            int t = t0 + tx * 4 + j;
            if (t >= N) continue;
            float v = acc[i][j];
            if (bias) v += bias[m];
            if (relu_out) v = fmaxf(v, 0.f);
            Y[(size_t)m * ldy + t] = v;
        }
    }
}

// ---------------------------------------------------------------------------
// Host orchestration (graph-capturable: kernel launches only).
// ---------------------------------------------------------------------------
extern "C" void kernel_launch(void* const* d_in, const int* in_sizes, int n_in,
                              void* d_out, int out_size) {
    (void)in_sizes; (void)n_in; (void)out_size;
    const float* input    = (const float*)d_in[0];
    const float* start_w  = (const float*)d_in[1];
    const float* filter_w = (const float*)d_in[2];
    const float* gate_w   = (const float*)d_in[3];
    const float* res_w    = (const float*)d_in[4];
    const float* skip_w   = (const float*)d_in[5];
    const float* end1_w   = (const float*)d_in[6];
    const float* end1_b   = (const float*)d_in[7];
    const float* end2_w   = (const float*)d_in[8];
    const float* end2_b   = (const float*)d_in[9];

    uint32_t *xHiA, *xLoA, *xHiB, *xLoB, *gHi, *gLo;
    uint32_t *wfgHi, *wfgLo, *resHi, *resLo, *skpHi, *skpLo;
    float *sk, *h1;
    cudaGetSymbolAddress((void**)&xHiA, g_xHiA);
    cudaGetSymbolAddress((void**)&xLoA, g_xLoA);
    cudaGetSymbolAddress((void**)&xHiB, g_xHiB);
    cudaGetSymbolAddress((void**)&xLoB, g_xLoB);
    cudaGetSymbolAddress((void**)&gHi,  g_gHi);
    cudaGetSymbolAddress((void**)&gLo,  g_gLo);
    cudaGetSymbolAddress((void**)&wfgHi, g_wfgHi);
    cudaGetSymbolAddress((void**)&wfgLo, g_wfgLo);
    cudaGetSymbolAddress((void**)&resHi, g_resHi);
    cudaGetSymbolAddress((void**)&resLo, g_resLo);
    cudaGetSymbolAddress((void**)&skpHi, g_skpHi);
    cudaGetSymbolAddress((void**)&skpLo, g_skpLo);
    cudaGetSymbolAddress((void**)&sk, g_sk);
    cudaGetSymbolAddress((void**)&h1, g_h1);

    // Weight fragment packing (every call; deterministic).
    {
        int n = NLAYER * 512 * 512 / 2;
        fragpack_gate<<<(n + 255) / 256, 256>>>(filter_w, gate_w, wfgHi, wfgLo);
        n = NLAYER * 256 * 256 / 2;
        fragpack_std<<<(n + 255) / 256, 256>>>(res_w, 256, 256, resHi, resLo);
        n = NLAYER * 512 * 256 / 2;
        fragpack_std<<<(n + 255) / 256, 256>>>(skip_w, 512, 256, skpHi, skpLo);
    }

    // Start conv: fp32 SIMT GEMM writing split bf16 planes directly.
    lin_start<<<dim3((7165 + 63) / 64, 4), 256>>>(
        start_w, input, xHiA, xLoA, 7165, ECOL - 7165);

    int L = 7165;
    uint32_t *xcHi = xHiA, *xcLo = xLoA, *xnHi = xHiB, *xnLo = xLoB;

    for (int i = 0; i < NLAYER; i++) {
        int d = 1 << (i % 10);
        int p = (d - (L % d)) % d;
        L += p;                     // virtual pad (masked in gate loads)
        int Nout = L - d;

        dim3 gg((Nout + 127) / 128, 8);
        gate_mma<<<gg, 128>>>(wfgHi + (size_t)i * 131072, wfgLo + (size_t)i * 131072,
                              xcHi, xcLo, gHi, gLo, L, d, p);

        dim3 gr((Nout + 127) / 128, 12);
        resskip_mma<<<gr, 128>>>(resHi + (size_t)i * 32768, resLo + (size_t)i * 32768,
                                 skpHi + (size_t)i * 65536, skpLo + (size_t)i * 65536,
                                 gHi, gLo, xcHi, xcLo, xnHi, xnLo,
                                 sk, Nout, i == 0 ? 1 : 0);
        uint32_t* t;
        t = xcHi; xcHi = xnHi; xnHi = t;
        t = xcLo; xcLo = xnLo; xnLo = t;
        L = Nout;
    }

    // End head on last 4096 columns (fp32 SIMT).
    lin_kernel<<<dim3(64, 8), 256>>>(
        end1_w, sk + (ECOL - 4096), LSTR, end1_b, h1, 4096,
        512, 512, 4096, 1, 1);
    lin_kernel<<<dim3(64, 4), 256>>>(
        end2_w, h1, 4096, end2_b, (float*)d_out, 4096,
        256, 512, 4096, 0, 0);
}